// round 13
// baseline (speedup 1.0000x reference)
#include <cuda_runtime.h>

#define NCH 27
#define HH 64
#define WW 64
#define OC 32
#define NB 2
#define PITCH 66            // floats per tile row; 66*4 % 8 == 0 -> LDS.64 stays aligned
#define PITCH8 33           // ull (pixel pairs) per tile row

typedef unsigned long long ull;

// pre-packed duplicated half-weights: per (oc, row=win 0..80):
//   g_w[idx*2+0] = { (w0/2,w0/2), (w1/2,w1/2) }
//   g_w[idx*2+1] = { (w2/2,w2/2), (-w0w1w2/2, -w0w1w2/2) }
__device__ ulonglong2 g_w[OC * 81 * 2];

__device__ __forceinline__ ull dupf(float v) {
    unsigned b = __float_as_uint(v);
    return ((ull)b << 32) | b;
}

__global__ void pack_weights_kernel(const float* __restrict__ w) {
    int i = blockIdx.x * blockDim.x + threadIdx.x;
    if (i < OC * 81) {
        const float* p = w + i * 3;            // [oc][win][3] contiguous
        float a = p[0], b = p[1], c = p[2];
        ulonglong2 lo, hi;
        lo.x = dupf(0.5f * a);
        lo.y = dupf(0.5f * b);
        hi.x = dupf(0.5f * c);
        hi.y = dupf(-0.5f * a * b * c);
        g_w[i * 2 + 0] = lo;
        g_w[i * 2 + 1] = hi;
    }
}

__device__ __forceinline__ ull addp(ull a, ull b) {
    ull r; asm("add.rn.f32x2 %0, %1, %2;" : "=l"(r) : "l"(a), "l"(b)); return r;
}
__device__ __forceinline__ ull mulp(ull a, ull b) {
    ull r; asm("mul.rn.f32x2 %0, %1, %2;" : "=l"(r) : "l"(a), "l"(b)); return r;
}
__device__ __forceinline__ ull fmap(ull a, ull b, ull c) {
    ull r; asm("fma.rn.f32x2 %0, %1, %2, %3;" : "=l"(r) : "l"(a), "l"(b), "l"(c)); return r;
}
__device__ __forceinline__ ull pack2u(unsigned lo, unsigned hi) {
    ull r; asm("mov.b64 %0, {%1, %2};" : "=l"(r) : "r"(lo), "r"(hi)); return r;
}
__device__ __forceinline__ void unpack2(ull v, unsigned& lo, unsigned& hi) {
    asm("mov.b64 {%0, %1}, %2;" : "=r"(lo), "=r"(hi) : "l"(v));
}

// packed maj3 on both lanes: 0.5*(a+b+c) - 0.5*(a*b*c)
__device__ __forceinline__ ull maj3p(ull a, ull b, ull c, ull h2, ull nh2) {
    ull s = addp(addp(a, b), c);
    ull q = mulp(mulp(a, b), c);
    return fmap(q, nh2, mulp(s, h2));
}

// grid (HH, OC/4, NB), 128 threads = 32 pixel-pairs x 4 ocs.
// Monolithic: full 81-row tile in smem (21.4KB), weights via L1-resident LDG,
// one __syncthreads, packed f32x2 tree.
__global__ __launch_bounds__(128, 7) void sconv_kernel(const float* __restrict__ x,
                                                       float* __restrict__ out) {
    __shared__ __align__(16) float tile[81 * PITCH];  // [row=c*3+r][col 0..65]; col0/col65 = zero halo

    const int h   = blockIdx.x;
    const int ocg = blockIdx.y;
    const int n   = blockIdx.z;
    const int tid = threadIdx.x;

    // halo columns (gw=-1, gw=64) are always outside the image -> zero
    for (int i = tid; i < 162; i += 128) {
        int row = i >> 1;
        tile[row * PITCH + ((i & 1) ? 65 : 0)] = 0.0f;
    }

    // interior: 81 rows x 64 cols (coalesced LDG -> STS)
    {
        const float* xb = x + (size_t)n * NCH * HH * WW;
        const int col = tid & 63;
#pragma unroll 4
        for (int row = tid >> 6; row < 81; row += 2) {
            int c  = row / 3;
            int r  = row - 3 * c;
            int gh = h + r - 1;
            float v = 0.0f;
            if ((unsigned)gh < (unsigned)HH)
                v = xb[c * (HH * WW) + gh * WW + col];
            tile[row * PITCH + 1 + col] = v;
        }
    }
    __syncthreads();

    const int p  = tid & 31;   // pixel pair: output cols 2p, 2p+1
    const int ol = tid >> 5;   // oc within group (uniform per warp)
    const ull* t8 = reinterpret_cast<const ull*>(tile);
    const ulonglong2* gw = g_w + (size_t)(ocg * 4 + ol) * 81 * 2;

    const ull h2  = pack2u(0x3F000000u, 0x3F000000u);   // (0.5, 0.5)
    const ull nh2 = pack2u(0xBF000000u, 0xBF000000u);   // (-0.5, -0.5)

    ull a3[3];
#pragma unroll
    for (int g3 = 0; g3 < 3; g3++) {
        ull a9[3];
#pragma unroll
        for (int g9 = 0; g9 < 3; g9++) {
            ull ch[3];
#pragma unroll
            for (int cc = 0; cc < 3; cc++) {
                const int c = g3 * 9 + g9 * 3 + cc;
                ull rr[3];
#pragma unroll
                for (int ki = 0; ki < 3; ki++) {
                    const int row = c * 3 + ki;
                    ull X0 = t8[row * PITCH8 + p];       // (t0 | t1), low word = lane 0
                    ull X2 = t8[row * PITCH8 + p + 1];   // (t2 | t3)
                    unsigned l0, h0, l2, h2b;
                    unpack2(X0, l0, h0);
                    unpack2(X2, l2, h2b);
                    (void)l0; (void)h2b;
                    ull X1 = pack2u(h0, l2);             // (t1 | t2)

                    ulonglong2 W01 = __ldg(gw + row * 2 + 0);  // (w0/2)x2, (w1/2)x2
                    ulonglong2 W23 = __ldg(gw + row * 2 + 1);  // (w2/2)x2, (-w0w1w2/2)x2

                    ull s = mulp(X0, W01.x);
                    s = fmap(X1, W01.y, s);
                    s = fmap(X2, W23.x, s);
                    ull P = mulp(mulp(X0, X1), X2);      // (t0t1t2 | t1t2t3)
                    rr[ki] = fmap(P, W23.y, s);          // folded leaf maj3
                }
                ch[cc] = maj3p(rr[0], rr[1], rr[2], h2, nh2);
            }
            a9[g9] = maj3p(ch[0], ch[1], ch[2], h2, nh2);
        }
        a3[g3] = maj3p(a9[0], a9[1], a9[2], h2, nh2);
    }
    ull res = maj3p(a3[0], a3[1], a3[2], h2, nh2);

    const int oc = ocg * 4 + ol;
    ull* op = reinterpret_cast<ull*>(out + (((size_t)n * OC + oc) * HH + h) * WW);
    op[p] = res;
}

extern "C" void kernel_launch(void* const* d_in, const int* in_sizes, int n_in,
                              void* d_out, int out_size) {
    const float* x = (const float*)d_in[0];
    const float* w = (const float*)d_in[1];
    float* out = (float*)d_out;

    pack_weights_kernel<<<(OC * 81 + 255) / 256, 256>>>(w);

    dim3 grid(HH, OC / 4, NB);
    sconv_kernel<<<grid, 128>>>(x, out);
}